// round 3
// baseline (speedup 1.0000x reference)
#include <cuda_runtime.h>
#include <math.h>

#define NB 4
#define ND 128
#define NT 4096
#define NK 64
#define NV 128

// Scratch (static device globals — no allocation in kernel_launch).
__device__ float g_W[256 * 128];          // rows: [0:64)=Wq, [64:128)=Wk, [128:256)=Wv
__device__ float g_bias[256];
__device__ float g_QKV[NB * NT * 256];    // per row: [Q(64) | K(64) | V(128)]
__device__ float g_colsum[NB * NT];
__device__ float g_Vs[NB * NT * NV];      // V scaled by 1/(8*colsum[t])

// ---------------------------------------------------------------------------
// m16n8k8 tf32 mma (row.col). Operands are fp32 bit patterns (HW truncates).
__device__ __forceinline__ void mma8(float* d, const unsigned* a, const unsigned* b) {
    asm volatile(
        "mma.sync.aligned.m16n8k8.row.col.f32.tf32.tf32.f32 "
        "{%0,%1,%2,%3}, {%4,%5,%6,%7}, {%8,%9}, {%0,%1,%2,%3};\n"
        : "+f"(d[0]), "+f"(d[1]), "+f"(d[2]), "+f"(d[3])
        : "r"(a[0]), "r"(a[1]), "r"(a[2]), "r"(a[3]), "r"(b[0]), "r"(b[1]));
}

// ---------------------------------------------------------------------------
// Kernel 0: pack weights/bias into one matrix, zero colsum accumulators.
__global__ void prep_kernel(const float* __restrict__ Wk, const float* __restrict__ bk,
                            const float* __restrict__ Wq, const float* __restrict__ bq,
                            const float* __restrict__ Wv, const float* __restrict__ bv) {
    int i = blockIdx.x * blockDim.x + threadIdx.x;   // [0, 16384)
    if (i < 64 * 128) {
        g_W[i] = Wq[i];
        g_W[64 * 128 + i] = Wk[i];
    }
    g_W[128 * 128 + i] = Wv[i];
    if (i < 64) { g_bias[i] = bq[i]; g_bias[64 + i] = bk[i]; }
    if (i < 128) g_bias[128 + i] = bv[i];
    if (i < NB * NT) g_colsum[i] = 0.0f;
}

// ---------------------------------------------------------------------------
// Kernel 1: QKV projection (fp32, small: ~1 GFLOP).
__global__ void qkv_kernel(const float* __restrict__ mb) {
    int n0 = blockIdx.x * 64;
    int m0 = blockIdx.y * 64;
    int b  = m0 >> 12;
    int t0 = m0 & (NT - 1);
    const float* x = mb + (size_t)b * ND * NT;

    __shared__ float Xs[64][33];
    __shared__ float Ws[64][33];

    int tid = threadIdx.x;
    int tx = tid & 15, ty = tid >> 4;
    float acc[4][4] = {};

    for (int k0 = 0; k0 < 128; k0 += 32) {
        {
            int r = tid & 63, kkb = tid >> 6;
#pragma unroll
            for (int i = 0; i < 8; i++) {
                int kk = kkb + i * 4;
                Xs[r][kk] = x[(k0 + kk) * NT + t0 + r];
            }
        }
        {
            int kk = tid & 31, nnb = tid >> 5;
#pragma unroll
            for (int i = 0; i < 8; i++) {
                int nn = nnb + i * 8;
                Ws[nn][kk] = g_W[(n0 + nn) * 128 + k0 + kk];
            }
        }
        __syncthreads();
#pragma unroll
        for (int k = 0; k < 32; k++) {
            float xv[4], wv[4];
#pragma unroll
            for (int i = 0; i < 4; i++) xv[i] = Xs[ty * 4 + i][k];
#pragma unroll
            for (int j = 0; j < 4; j++) wv[j] = Ws[tx * 4 + j][k];
#pragma unroll
            for (int i = 0; i < 4; i++)
#pragma unroll
                for (int j = 0; j < 4; j++) acc[i][j] += xv[i] * wv[j];
        }
        __syncthreads();
    }
#pragma unroll
    for (int i = 0; i < 4; i++) {
        int r = ty * 4 + i;
        float* dst = g_QKV + (size_t)(m0 + r) * 256;
#pragma unroll
        for (int j = 0; j < 4; j++) {
            int n = n0 + tx * 4 + j;
            dst[n] = acc[i][j] + g_bias[n];
        }
    }
}

// ---------------------------------------------------------------------------
// Kernel 2: colsum[b][t] = sum_{q >= t} exp(Q[q].K[t])  — tf32 mma version.
// grid: (t-tile 64, b 4, q-chunk 8 of 512 rows). 256 threads = 8 warps.
// Warp layout over 64x64 S tile: wr = w&1 (32 q-rows), wc = w>>1 (16 t-cols).
__global__ void colsum_kernel() {
    const int QCHUNK = 512;
    int t0 = blockIdx.x * 64;
    int b  = blockIdx.y;
    int qlo = blockIdx.z * QCHUNK;
    if (qlo + QCHUNK - 1 < t0) return;

    __shared__ float Ks[64 * 68];
    __shared__ float Qs[64 * 68];
    __shared__ float cs[64];

    const float* qkv = g_QKV + (size_t)b * NT * 256;
    int tid = threadIdx.x;
    int lane = tid & 31, w = tid >> 5;
    int g = lane >> 2, tg = lane & 3;
    int wr = w & 1, wc = w >> 1;

    {   // K tile, float4 coalesced
        int f4 = tid & 15, r0 = tid >> 4;
#pragma unroll
        for (int i = 0; i < 4; i++) {
            int r = r0 + 16 * i;
            *(float4*)&Ks[r * 68 + f4 * 4] = *(const float4*)&qkv[(t0 + r) * 256 + 64 + f4 * 4];
        }
    }
    if (tid < 64) cs[tid] = 0.0f;
    __syncthreads();

    // Hoist K (B-operand) fragments: tile fixed for the whole block.
    unsigned bf[2][8][2];
#pragma unroll
    for (int ni = 0; ni < 2; ni++)
#pragma unroll
        for (int kk = 0; kk < 8; kk++) {
            int trow = wc * 16 + ni * 8 + g;
            bf[ni][kk][0] = __float_as_uint(Ks[trow * 68 + kk * 8 + tg]);
            bf[ni][kk][1] = __float_as_uint(Ks[trow * 68 + kk * 8 + tg + 4]);
        }

    float colacc[2][2] = {};

    for (int q0 = qlo; q0 < qlo + QCHUNK; q0 += 64) {
        if (q0 + 63 < t0) continue;   // block-uniform skip
        __syncthreads();
        {   // Q tile
            int f4 = tid & 15, r0 = tid >> 4;
#pragma unroll
            for (int i = 0; i < 4; i++) {
                int r = r0 + 16 * i;
                *(float4*)&Qs[r * 68 + f4 * 4] = *(const float4*)&qkv[(q0 + r) * 256 + f4 * 4];
            }
        }
        __syncthreads();

        float d[2][2][4] = {};
#pragma unroll
        for (int kk = 0; kk < 8; kk++) {
            unsigned a[2][4];
#pragma unroll
            for (int mi = 0; mi < 2; mi++) {
                int r = wr * 32 + mi * 16;
                a[mi][0] = __float_as_uint(Qs[(r + g) * 68 + kk * 8 + tg]);
                a[mi][1] = __float_as_uint(Qs[(r + g + 8) * 68 + kk * 8 + tg]);
                a[mi][2] = __float_as_uint(Qs[(r + g) * 68 + kk * 8 + tg + 4]);
                a[mi][3] = __float_as_uint(Qs[(r + g + 8) * 68 + kk * 8 + tg + 4]);
            }
#pragma unroll
            for (int mi = 0; mi < 2; mi++)
#pragma unroll
                for (int ni = 0; ni < 2; ni++)
                    mma8(d[mi][ni], a[mi], bf[ni][kk]);
        }
        // mask + exp + per-thread column accumulate
#pragma unroll
        for (int mi = 0; mi < 2; mi++)
#pragma unroll
            for (int ni = 0; ni < 2; ni++)
#pragma unroll
                for (int e = 0; e < 4; e++) {
                    int row = q0 + wr * 32 + mi * 16 + g + (e >> 1) * 8;
                    int col = t0 + wc * 16 + ni * 8 + 2 * tg + (e & 1);
                    if (row >= col) colacc[ni][e & 1] += __expf(d[mi][ni][e]);
                }
    }

    // reduce over g (lanes differing in bits 2..4), then atomics
#pragma unroll
    for (int ni = 0; ni < 2; ni++)
#pragma unroll
        for (int j = 0; j < 2; j++) {
            float v = colacc[ni][j];
            v += __shfl_xor_sync(0xffffffffu, v, 4);
            v += __shfl_xor_sync(0xffffffffu, v, 8);
            v += __shfl_xor_sync(0xffffffffu, v, 16);
            colacc[ni][j] = v;
        }
    if (g == 0) {
#pragma unroll
        for (int ni = 0; ni < 2; ni++) {
            atomicAdd(&cs[wc * 16 + ni * 8 + 2 * tg], colacc[ni][0]);
            atomicAdd(&cs[wc * 16 + ni * 8 + 2 * tg + 1], colacc[ni][1]);
        }
    }
    __syncthreads();
    if (tid < 64) atomicAdd(&g_colsum[b * NT + t0 + tid], cs[tid]);
}

// ---------------------------------------------------------------------------
// Kernel 3: g_Vs[b][t][v] = V[b][t][v] / (8 * colsum[b][t])
__global__ void scalev_kernel() {
    int idx = blockIdx.x * 256 + threadIdx.x;
    int t = (idx >> 7) & (NT - 1);
    int b = idx >> 19;
    int v = idx & 127;
    float inv = 1.0f / (8.0f * g_colsum[b * NT + t]);
    g_Vs[idx] = g_QKV[(((size_t)b * NT + t) << 8) + 128 + v] * inv;
}

// ---------------------------------------------------------------------------
// Kernel 4: read[q,:] = sum_{t<=q} exp(Q[q].K[t]) * Vs[t,:], out = (x+read)^T
// tf32 mma for both S and E@V. 256 threads, Q fragments hoisted.
__global__ void attn_kernel(const float* __restrict__ mb, float* __restrict__ out) {
    extern __shared__ float sm[];
    float* Qs  = sm;              // 64*68
    float* Ks  = Qs + 64 * 68;    // 64*68
    float* Es  = Ks + 64 * 68;    // 64*68
    float* Vss = Es + 64 * 68;    // 64*136 (reused as output stage)

    int xx = blockIdx.x;
    int qt = (xx & 1) ? (63 - (xx >> 1)) : (xx >> 1);   // interleave long/short
    int b = blockIdx.y;
    int q0 = qt * 64;
    const float* qkv = g_QKV + (size_t)b * NT * 256;
    int tid = threadIdx.x;
    int lane = tid & 31, w = tid >> 5;
    int g = lane >> 2, tg = lane & 3;
    int wr = w & 1, wc = w >> 1;

    {   // Q tile (persistent)
        int f4 = tid & 15, r0 = tid >> 4;
#pragma unroll
        for (int i = 0; i < 4; i++) {
            int r = r0 + 16 * i;
            *(float4*)&Qs[r * 68 + f4 * 4] = *(const float4*)&qkv[(q0 + r) * 256 + f4 * 4];
        }
    }
    __syncthreads();

    // Hoist Q (A-operand) fragments: fixed across the whole t-loop.
    unsigned qa[2][8][4];
#pragma unroll
    for (int mi = 0; mi < 2; mi++)
#pragma unroll
        for (int kk = 0; kk < 8; kk++) {
            int r = wr * 32 + mi * 16;
            qa[mi][kk][0] = __float_as_uint(Qs[(r + g) * 68 + kk * 8 + tg]);
            qa[mi][kk][1] = __float_as_uint(Qs[(r + g + 8) * 68 + kk * 8 + tg]);
            qa[mi][kk][2] = __float_as_uint(Qs[(r + g) * 68 + kk * 8 + tg + 4]);
            qa[mi][kk][3] = __float_as_uint(Qs[(r + g + 8) * 68 + kk * 8 + tg + 4]);
        }

    float acc[2][4][4] = {};   // EV accumulator: rows wr*32+mi*16+{g,g+8}, cols wc*32+ni*8+2tg+{0,1}

    for (int tt = 0; tt <= qt; tt++) {
        int t0 = tt * 64;
        __syncthreads();    // protect Ks/Vss/Es from previous iteration's readers
        {   // K tile
            int f4 = tid & 15, r0 = tid >> 4;
#pragma unroll
            for (int i = 0; i < 4; i++) {
                int r = r0 + 16 * i;
                *(float4*)&Ks[r * 68 + f4 * 4] = *(const float4*)&qkv[(t0 + r) * 256 + 64 + f4 * 4];
            }
        }
        {   // Vs tile
            const float4* src = (const float4*)(g_Vs + ((size_t)b * NT + t0) * NV);
            int v4 = tid & 31, r0 = tid >> 5;
#pragma unroll
            for (int i = 0; i < 8; i++) {
                int r = r0 + 8 * i;
                *(float4*)&Vss[r * 136 + v4 * 4] = src[r * 32 + v4];
            }
        }
        __syncthreads();

        // Stage A: S = Q K^T  ->  Es = exp(masked S)
        {
            float d[2][2][4] = {};
#pragma unroll
            for (int kk = 0; kk < 8; kk++) {
                unsigned bfr[2][2];
#pragma unroll
                for (int ni = 0; ni < 2; ni++) {
                    int trow = wc * 16 + ni * 8 + g;
                    bfr[ni][0] = __float_as_uint(Ks[trow * 68 + kk * 8 + tg]);
                    bfr[ni][1] = __float_as_uint(Ks[trow * 68 + kk * 8 + tg + 4]);
                }
#pragma unroll
                for (int mi = 0; mi < 2; mi++)
#pragma unroll
                    for (int ni = 0; ni < 2; ni++)
                        mma8(d[mi][ni], qa[mi][kk], bfr[ni]);
            }
            bool diag = (tt == qt);
#pragma unroll
            for (int mi = 0; mi < 2; mi++)
#pragma unroll
                for (int ni = 0; ni < 2; ni++)
#pragma unroll
                    for (int e2 = 0; e2 < 2; e2++) {
                        int rloc = wr * 32 + mi * 16 + g + e2 * 8;
                        int cloc = wc * 16 + ni * 8 + 2 * tg;
                        float v0 = __expf(d[mi][ni][e2 * 2 + 0]);
                        float v1 = __expf(d[mi][ni][e2 * 2 + 1]);
                        if (diag) {
                            if (cloc > rloc) v0 = 0.0f;
                            if (cloc + 1 > rloc) v1 = 0.0f;
                        }
                        *(float2*)&Es[rloc * 68 + cloc] = make_float2(v0, v1);
                    }
        }
        __syncthreads();

        // Stage B: acc += Es @ Vss
#pragma unroll
        for (int kk = 0; kk < 8; kk++) {
            unsigned a[2][4], bfr[4][2];
#pragma unroll
            for (int mi = 0; mi < 2; mi++) {
                int r = wr * 32 + mi * 16;
                a[mi][0] = __float_as_uint(Es[(r + g) * 68 + kk * 8 + tg]);
                a[mi][1] = __float_as_uint(Es[(r + g + 8) * 68 + kk * 8 + tg]);
                a[mi][2] = __float_as_uint(Es[(r + g) * 68 + kk * 8 + tg + 4]);
                a[mi][3] = __float_as_uint(Es[(r + g + 8) * 68 + kk * 8 + tg + 4]);
            }
#pragma unroll
            for (int ni = 0; ni < 4; ni++) {
                int vcol = wc * 32 + ni * 8 + g;
                bfr[ni][0] = __float_as_uint(Vss[(kk * 8 + tg) * 136 + vcol]);
                bfr[ni][1] = __float_as_uint(Vss[(kk * 8 + tg + 4) * 136 + vcol]);
            }
#pragma unroll
            for (int mi = 0; mi < 2; mi++)
#pragma unroll
                for (int ni = 0; ni < 4; ni++)
                    mma8(acc[mi][ni], a[mi], bfr[ni]);
        }
    }

    __syncthreads();
    // Stage accumulator into smem (reuse Vss) so final [d][t] writes coalesce over t.
#pragma unroll
    for (int mi = 0; mi < 2; mi++)
#pragma unroll
        for (int ni = 0; ni < 4; ni++)
#pragma unroll
            for (int e2 = 0; e2 < 2; e2++) {
                int rloc = wr * 32 + mi * 16 + g + e2 * 8;
                int cloc = wc * 32 + ni * 8 + 2 * tg;
                *(float2*)&Vss[rloc * 136 + cloc] =
                    make_float2(acc[mi][ni][e2 * 2], acc[mi][ni][e2 * 2 + 1]);
            }
    __syncthreads();
    {
        int qq = tid & 63, db = tid >> 6;
        const float* xin = mb + (size_t)b * ND * NT;
        float* o = out + (size_t)b * ND * NT;
#pragma unroll
        for (int i = 0; i < 32; i++) {
            int d_ = db + i * 4;
            o[d_ * NT + q0 + qq] = xin[d_ * NT + q0 + qq] + Vss[qq * 136 + d_];
        }
    }
}

// ---------------------------------------------------------------------------
#define ATT_SMEM ((64 * 68 * 3 + 64 * 136) * 4)   // 87040 bytes

extern "C" void kernel_launch(void* const* d_in, const int* in_sizes, int n_in,
                              void* d_out, int out_size) {
    const float* mb = (const float*)d_in[0];
    const float* Wk = (const float*)d_in[1];
    const float* bk = (const float*)d_in[2];
    const float* Wq = (const float*)d_in[3];
    const float* bq = (const float*)d_in[4];
    const float* Wv = (const float*)d_in[5];
    const float* bv = (const float*)d_in[6];
    float* out = (float*)d_out;

    cudaFuncSetAttribute(attn_kernel, cudaFuncAttributeMaxDynamicSharedMemorySize, ATT_SMEM);

    prep_kernel<<<64, 256>>>(Wk, bk, Wq, bq, Wv, bv);
    qkv_kernel<<<dim3(4, 256), 256>>>(mb);
    colsum_kernel<<<dim3(64, 4, 8), 256>>>();
    scalev_kernel<<<(NB * NT * NV) / 256, 256>>>();
    attn_kernel<<<dim3(64, 4), 256, ATT_SMEM>>>(mb, out);
}

// round 5
// speedup vs baseline: 1.5483x; 1.5483x over previous
#include <cuda_runtime.h>
#include <cuda_bf16.h>
#include <math.h>

#define NB 4
#define ND 128
#define NT 4096
#define NK 64
#define NV 128

__device__ float g_W[256 * 128];
__device__ float g_bias[256];
__device__ float g_QKV[NB * NT * 256];   // per row: [Q(64) | K(64) | V(128)]
__device__ float g_colsum[NB * NT];
__device__ __nv_bfloat16 g_Vsb[NB * NT * NV];  // V/(8*colsum) bf16, [b][t][v]

// ---------------------------------------------------------------------------
__device__ __forceinline__ void mma8(float* d, const unsigned* a, const unsigned* b) {
    asm volatile(
        "mma.sync.aligned.m16n8k8.row.col.f32.tf32.tf32.f32 "
        "{%0,%1,%2,%3}, {%4,%5,%6,%7}, {%8,%9}, {%0,%1,%2,%3};\n"
        : "+f"(d[0]), "+f"(d[1]), "+f"(d[2]), "+f"(d[3])
        : "r"(a[0]), "r"(a[1]), "r"(a[2]), "r"(a[3]), "r"(b[0]), "r"(b[1]));
}
__device__ __forceinline__ void mma16(float* d, const unsigned* a, const unsigned* b) {
    asm volatile(
        "mma.sync.aligned.m16n8k16.row.col.f32.bf16.bf16.f32 "
        "{%0,%1,%2,%3}, {%4,%5,%6,%7}, {%8,%9}, {%0,%1,%2,%3};\n"
        : "+f"(d[0]), "+f"(d[1]), "+f"(d[2]), "+f"(d[3])
        : "r"(a[0]), "r"(a[1]), "r"(a[2]), "r"(a[3]), "r"(b[0]), "r"(b[1]));
}
__device__ __forceinline__ unsigned packbf(float lo, float hi) {
    unsigned r;
    asm("cvt.rn.bf16x2.f32 %0, %1, %2;" : "=r"(r) : "f"(hi), "f"(lo));
    return r;
}
__device__ __forceinline__ void ldsm4t(unsigned* r, unsigned addr) {
    asm volatile("ldmatrix.sync.aligned.m8n8.x4.trans.shared.b16 {%0,%1,%2,%3}, [%4];"
                 : "=r"(r[0]), "=r"(r[1]), "=r"(r[2]), "=r"(r[3]) : "r"(addr));
}
__device__ __forceinline__ void cpa16(unsigned saddr, const void* gsrc) {
    asm volatile("cp.async.cg.shared.global [%0], [%1], 16;" :: "r"(saddr), "l"(gsrc));
}
__device__ __forceinline__ void cpcommit() { asm volatile("cp.async.commit_group;"); }
template <int N>
__device__ __forceinline__ void cpwait() { asm volatile("cp.async.wait_group %0;" :: "n"(N)); }
__device__ __forceinline__ unsigned fas(float x) { return __float_as_uint(x); }

// ---------------------------------------------------------------------------
__global__ void prep_kernel(const float* __restrict__ Wk, const float* __restrict__ bk,
                            const float* __restrict__ Wq, const float* __restrict__ bq,
                            const float* __restrict__ Wv, const float* __restrict__ bv) {
    int i = blockIdx.x * blockDim.x + threadIdx.x;   // [0, 16384)
    if (i < 64 * 128) { g_W[i] = Wq[i]; g_W[64 * 128 + i] = Wk[i]; }
    g_W[128 * 128 + i] = Wv[i];
    if (i < 64) { g_bias[i] = bq[i]; g_bias[64 + i] = bk[i]; }
    if (i < 128) g_bias[128 + i] = bv[i];
    if (i < NB * NT) g_colsum[i] = 0.0f;
}

// ---------------------------------------------------------------------------
// QKV projection (fp32 SIMT; ~1 GFLOP)
__global__ void qkv_kernel(const float* __restrict__ mb) {
    int n0 = blockIdx.x * 64, m0 = blockIdx.y * 64;
    int b = m0 >> 12, t0 = m0 & (NT - 1);
    const float* x = mb + (size_t)b * ND * NT;
    __shared__ float Xs[64][33];
    __shared__ float Ws[64][33];
    int tid = threadIdx.x, tx = tid & 15, ty = tid >> 4;
    float acc[4][4] = {};
    for (int k0 = 0; k0 < 128; k0 += 32) {
        { int r = tid & 63, kkb = tid >> 6;
#pragma unroll
          for (int i = 0; i < 8; i++) { int kk = kkb + i * 4; Xs[r][kk] = x[(k0 + kk) * NT + t0 + r]; } }
        { int kk = tid & 31, nnb = tid >> 5;
#pragma unroll
          for (int i = 0; i < 8; i++) { int nn = nnb + i * 8; Ws[nn][kk] = g_W[(n0 + nn) * 128 + k0 + kk]; } }
        __syncthreads();
#pragma unroll
        for (int k = 0; k < 32; k++) {
            float xv[4], wv[4];
#pragma unroll
            for (int i = 0; i < 4; i++) xv[i] = Xs[ty * 4 + i][k];
#pragma unroll
            for (int j = 0; j < 4; j++) wv[j] = Ws[tx * 4 + j][k];
#pragma unroll
            for (int i = 0; i < 4; i++)
#pragma unroll
                for (int j = 0; j < 4; j++) acc[i][j] += xv[i] * wv[j];
        }
        __syncthreads();
    }
#pragma unroll
    for (int i = 0; i < 4; i++) {
        float* dst = g_QKV + (size_t)(m0 + ty * 4 + i) * 256;
#pragma unroll
        for (int j = 0; j < 4; j++) { int n = n0 + tx * 4 + j; dst[n] = acc[i][j] + g_bias[n]; }
    }
}

// ---------------------------------------------------------------------------
// colsum[b][t] = sum_{q>=t} exp(Q[q].K[t]) — tf32 mma + cp.async pipelined Q.
// Dynamic smem: Ks[4352] | Qbuf0[4352] | Qbuf1[4352] | cs[64]  = 52736 bytes
#define CS_SMEM ((4352 * 3 + 64) * 4)

__global__ __launch_bounds__(256) void colsum_kernel() {
    const int QCHUNK = 512;
    int t0 = blockIdx.x * 64, b = blockIdx.y, qlo = blockIdx.z * QCHUNK;
    if (qlo + QCHUNK - 1 < t0) return;
    extern __shared__ float sm[];
    float* Ks = sm;
    float* cs = sm + 4352 * 3;
    const float* qkv = g_QKV + (size_t)b * NT * 256;
    int tid = threadIdx.x, lane = tid & 31, w = tid >> 5;
    int g = lane >> 2, tg = lane & 3, wr = w & 1, wc = w >> 1;
    unsigned sb = (unsigned)__cvta_generic_to_shared(sm);

    { int c = tid & 15, r0 = tid >> 4;
#pragma unroll
      for (int i = 0; i < 4; i++) { int r = r0 + 16 * i;
          *(float4*)&Ks[r * 68 + c * 4] = *(const float4*)&qkv[(t0 + r) * 256 + 64 + c * 4]; } }
    if (tid < 64) cs[tid] = 0.0f;
    { int c = tid & 15, r0 = tid >> 4;   // prefetch first Q tile -> buf0
#pragma unroll
      for (int i = 0; i < 4; i++) { int r = r0 + 16 * i;
          cpa16(sb + (4352 + r * 68 + c * 4) * 4, qkv + (size_t)(qlo + r) * 256 + c * 4); } }
    cpcommit();
    __syncthreads();

    unsigned bf[2][8][2];
#pragma unroll
    for (int ni = 0; ni < 2; ni++)
#pragma unroll
        for (int kk = 0; kk < 8; kk++) {
            int trow = wc * 16 + ni * 8 + g;
            bf[ni][kk][0] = fas(Ks[trow * 68 + kk * 8 + tg]);
            bf[ni][kk][1] = fas(Ks[trow * 68 + kk * 8 + tg + 4]);
        }

    float colacc[2][2] = {};
    int buf = 0;
    for (int q0 = qlo; q0 < qlo + QCHUNK; q0 += 64) {
        if (q0 + 64 < qlo + QCHUNK) {
            int c = tid & 15, r0 = tid >> 4, bo = buf ^ 1;
#pragma unroll
            for (int i = 0; i < 4; i++) { int r = r0 + 16 * i;
                cpa16(sb + (4352 * (1 + bo) + r * 68 + c * 4) * 4,
                      qkv + (size_t)(q0 + 64 + r) * 256 + c * 4); }
        }
        cpcommit(); cpwait<1>(); __syncthreads();
        if (q0 + 63 >= t0) {
            const float* Qs = sm + 4352 * (1 + buf);
            float d[2][2][4] = {};
#pragma unroll
            for (int kk = 0; kk < 8; kk++) {
                unsigned a[2][4];
#pragma unroll
                for (int mi = 0; mi < 2; mi++) {
                    int r = wr * 32 + mi * 16;
                    a[mi][0] = fas(Qs[(r + g) * 68 + kk * 8 + tg]);
                    a[mi][1] = fas(Qs[(r + g + 8) * 68 + kk * 8 + tg]);
                    a[mi][2] = fas(Qs[(r + g) * 68 + kk * 8 + tg + 4]);
                    a[mi][3] = fas(Qs[(r + g + 8) * 68 + kk * 8 + tg + 4]);
                }
#pragma unroll
                for (int mi = 0; mi < 2; mi++)
#pragma unroll
                    for (int ni = 0; ni < 2; ni++)
                        mma8(d[mi][ni], a[mi], bf[ni][kk]);
            }
#pragma unroll
            for (int mi = 0; mi < 2; mi++)
#pragma unroll
                for (int ni = 0; ni < 2; ni++)
#pragma unroll
                    for (int e = 0; e < 4; e++) {
                        int row = q0 + wr * 32 + mi * 16 + g + (e >> 1) * 8;
                        int col = t0 + wc * 16 + ni * 8 + 2 * tg + (e & 1);
                        if (row >= col) colacc[ni][e & 1] += __expf(d[mi][ni][e]);
                    }
        }
        __syncthreads();
        buf ^= 1;
    }
#pragma unroll
    for (int ni = 0; ni < 2; ni++)
#pragma unroll
        for (int j = 0; j < 2; j++) {
            float v = colacc[ni][j];
            v += __shfl_xor_sync(0xffffffffu, v, 4);
            v += __shfl_xor_sync(0xffffffffu, v, 8);
            v += __shfl_xor_sync(0xffffffffu, v, 16);
            colacc[ni][j] = v;
        }
    if (g == 0)
#pragma unroll
        for (int ni = 0; ni < 2; ni++) {
            atomicAdd(&cs[wc * 16 + ni * 8 + 2 * tg], colacc[ni][0]);
            atomicAdd(&cs[wc * 16 + ni * 8 + 2 * tg + 1], colacc[ni][1]);
        }
    __syncthreads();
    if (tid < 64) atomicAdd(&g_colsum[b * NT + t0 + tid], cs[tid]);
}

// ---------------------------------------------------------------------------
// scalev: g_Vsb[b][t][v] = bf16( V / (8*colsum) )
__global__ void scalev_kernel() {
    int idx = blockIdx.x * 256 + threadIdx.x;   // [0, 4*4096*64)
    int v2 = idx & 63;
    int t = (idx >> 6) & (NT - 1);
    int b = idx >> 18;
    float inv = 1.0f / (8.0f * g_colsum[b * NT + t]);
    const float* src = &g_QKV[(((size_t)b * NT + t) << 8) + 128 + v2 * 2];
    __nv_bfloat162 o;
    o.x = __float2bfloat16(src[0] * inv);
    o.y = __float2bfloat16(src[1] * inv);
    ((__nv_bfloat162*)g_Vsb)[((size_t)b * NT + t) * 64 + v2] = o;
}

// ---------------------------------------------------------------------------
// attn: block xx handles q-tiles (xx, 63-xx). Warps 0-3 -> tile A, 4-7 -> tile B.
// S in tf32 regs -> exp -> bf16 A-frags -> EV mma with ldmatrix'd bf16 V.
// smem floats: [0,8704) Q tiles, [8704,17408) K double buf, bytes 69632.. V double buf.
#define AT_KOFF 8704
#define AT_VBYTE 69632
#define ATT_SMEM 104448

__global__ __launch_bounds__(256, 1) void attn_kernel(const float* __restrict__ mb,
                                                      float* __restrict__ out) {
    extern __shared__ float sm[];
    int xx = blockIdx.x, b = blockIdx.y;
    int qtA = xx, qtB = 63 - xx;
    int q0A = qtA * 64, q0B = qtB * 64;
    const float* qkv = g_QKV + (size_t)b * NT * 256;
    const __nv_bfloat16* vsb = g_Vsb + (size_t)b * NT * NV;
    int tid = threadIdx.x, lane = tid & 31, w = tid >> 5;
    int g = lane >> 2, tg = lane & 3;
    int gid = w >> 2, wg = w & 3;
    int myqt = gid ? qtB : qtA;
    unsigned sb = (unsigned)__cvta_generic_to_shared(sm);

    // load both Q tiles (fp32)
#pragma unroll
    for (int i = 0; i < 8; i++) {
        int idx = tid + 256 * i;                 // 0..2047
        int grp = idx >> 10, r = (idx >> 4) & 63, c = idx & 15;
        int q0g = grp ? q0B : q0A;
        *(float4*)&sm[grp * 4352 + r * 68 + c * 4] =
            *(const float4*)&qkv[(size_t)(q0g + r) * 256 + c * 4];
    }
    // prefetch tile 0 (K fp32 + V bf16)
#pragma unroll
    for (int i = 0; i < 4; i++) { int idx = tid + 256 * i; int r = idx >> 4, c = idx & 15;
        cpa16(sb + (AT_KOFF + r * 68 + c * 4) * 4, qkv + (size_t)r * 256 + 64 + c * 4); }
#pragma unroll
    for (int i = 0; i < 4; i++) { int idx = tid + 256 * i; int r = idx >> 4, c = idx & 15;
        cpa16(sb + AT_VBYTE + (r * 136 + c * 8) * 2, vsb + (size_t)r * 128 + c * 8); }
    cpcommit();
    __syncthreads();

    // hoist Q A-fragments (tf32)
    const float* myQ = sm + gid * 4352;
    unsigned qa_[8][4];
#pragma unroll
    for (int kk = 0; kk < 8; kk++) {
        qa_[kk][0] = fas(myQ[(wg * 16 + g) * 68 + kk * 8 + tg]);
        qa_[kk][1] = fas(myQ[(wg * 16 + g + 8) * 68 + kk * 8 + tg]);
        qa_[kk][2] = fas(myQ[(wg * 16 + g) * 68 + kk * 8 + tg + 4]);
        qa_[kk][3] = fas(myQ[(wg * 16 + g + 8) * 68 + kk * 8 + tg + 4]);
    }

    float acc[16][4] = {};
    int buf = 0;
    int sub = lane >> 3, li = lane & 7;
    for (int tt = 0; tt <= qtB; tt++) {
        if (tt < qtB) {
            int t1 = (tt + 1) * 64, bo = buf ^ 1;
#pragma unroll
            for (int i = 0; i < 4; i++) { int idx = tid + 256 * i; int r = idx >> 4, c = idx & 15;
                cpa16(sb + (AT_KOFF + bo * 4352 + r * 68 + c * 4) * 4,
                      qkv + (size_t)(t1 + r) * 256 + 64 + c * 4); }
#pragma unroll
            for (int i = 0; i < 4; i++) { int idx = tid + 256 * i; int r = idx >> 4, c = idx & 15;
                cpa16(sb + AT_VBYTE + bo * 17408 + (r * 136 + c * 8) * 2,
                      vsb + (size_t)(t1 + r) * 128 + c * 8); }
        }
        cpcommit(); cpwait<1>(); __syncthreads();

        if (tt <= myqt) {
            const float* Kb = sm + AT_KOFF + buf * 4352;
            float d[8][4] = {};
#pragma unroll
            for (int kk = 0; kk < 8; kk++)
#pragma unroll
                for (int ni = 0; ni < 8; ni++) {
                    unsigned b2[2] = { fas(Kb[(ni * 8 + g) * 68 + kk * 8 + tg]),
                                       fas(Kb[(ni * 8 + g) * 68 + kk * 8 + tg + 4]) };
                    mma8(d[ni], qa_[kk], b2);
                }
            bool diag = (tt == myqt);
            unsigned Af[4][4];
#pragma unroll
            for (int ni = 0; ni < 8; ni++) {
                float e[4];
#pragma unroll
                for (int c = 0; c < 4; c++) {
                    int row = wg * 16 + g + (c >> 1) * 8;
                    int col = ni * 8 + 2 * tg + (c & 1);
                    float v = __expf(d[ni][c]);
                    e[c] = (diag && col > row) ? 0.0f : v;
                }
                Af[ni >> 1][(ni & 1) * 2 + 0] = packbf(e[0], e[1]);
                Af[ni >> 1][(ni & 1) * 2 + 1] = packbf(e[2], e[3]);
            }
#pragma unroll
            for (int kc = 0; kc < 4; kc++)
#pragma unroll
                for (int nj = 0; nj < 8; nj++) {
                    unsigned r4[4];
                    unsigned addr = sb + AT_VBYTE + buf * 17408 +
                        ((kc * 16 + (sub & 1) * 8 + li) * 136 + nj * 16 + (sub >> 1) * 8) * 2;
                    ldsm4t(r4, addr);
                    mma16(acc[nj * 2 + 0], Af[kc], &r4[0]);
                    mma16(acc[nj * 2 + 1], Af[kc], &r4[2]);
                }
        }
        __syncthreads();
        buf ^= 1;
    }

    // epilogue: stage (stride 133 -> conflict-free transpose read), add residual, write
    float* stg = gid ? (sm + 8704) : sm;
#pragma unroll
    for (int nj = 0; nj < 16; nj++)
#pragma unroll
        for (int c = 0; c < 4; c++) {
            int row = wg * 16 + g + (c >> 1) * 8;
            int col = nj * 8 + 2 * tg + (c & 1);
            stg[row * 133 + col] = acc[nj][c];
        }
    __syncthreads();
    {
        int gw = tid >> 7, gtid = tid & 127;
        int qq = gtid & 63, db = gtid >> 6;
        const float* s2 = gw ? (sm + 8704) : sm;
        int q0w = gw ? q0B : q0A;
        const float* xin = mb + (size_t)b * ND * NT;
        float* o = out + (size_t)b * ND * NT;
#pragma unroll
        for (int i = 0; i < 64; i++) {
            int d_ = db + i * 2;
            o[d_ * NT + q0w + qq] = xin[d_ * NT + q0w + qq] + s2[qq * 133 + d_];
        }
    }
}

// ---------------------------------------------------------------------------
extern "C" void kernel_launch(void* const* d_in, const int* in_sizes, int n_in,
                              void* d_out, int out_size) {
    const float* mb = (const float*)d_in[0];
    const float* Wk = (const float*)d_in[1];
    const float* bk = (const float*)d_in[2];
    const float* Wq = (const float*)d_in[3];
    const float* bq = (const float*)d_in[4];
    const float* Wv = (const float*)d_in[5];
    const float* bv = (const float*)d_in[6];
    float* out = (float*)d_out;

    cudaFuncSetAttribute(colsum_kernel, cudaFuncAttributeMaxDynamicSharedMemorySize, CS_SMEM);
    cudaFuncSetAttribute(attn_kernel, cudaFuncAttributeMaxDynamicSharedMemorySize, ATT_SMEM);

    prep_kernel<<<64, 256>>>(Wk, bk, Wq, bq, Wv, bv);
    qkv_kernel<<<dim3(4, 256), 256>>>(mb);
    colsum_kernel<<<dim3(64, 4, 8), 256, CS_SMEM>>>();
    scalev_kernel<<<(NB * NT * 64) / 256, 256>>>();
    attn_kernel<<<dim3(32, 4), 256, ATT_SMEM>>>(mb, out);
}

// round 6
// speedup vs baseline: 2.0303x; 1.3113x over previous
#include <cuda_runtime.h>
#include <cuda_bf16.h>
#include <math.h>

#define NB 4
#define ND 128
#define NT 4096
#define NK 64
#define NV 128

__device__ float g_W[256 * 128];
__device__ float g_bias[256];
__device__ __nv_bfloat16 g_QKb[NB * NT * 128];  // per row: [Q(64)|K(64)] bf16
__device__ float g_Vf[NB * NT * 128];           // V fp32
__device__ float g_colsum[NB * NT];
__device__ __nv_bfloat16 g_Vsb[NB * NT * NV];   // V/(8*colsum) bf16, [b][t][v]

// ---------------------------------------------------------------------------
__device__ __forceinline__ void mma8(float* d, const unsigned* a, const unsigned* b) {
    asm volatile(
        "mma.sync.aligned.m16n8k8.row.col.f32.tf32.tf32.f32 "
        "{%0,%1,%2,%3}, {%4,%5,%6,%7}, {%8,%9}, {%0,%1,%2,%3};\n"
        : "+f"(d[0]), "+f"(d[1]), "+f"(d[2]), "+f"(d[3])
        : "r"(a[0]), "r"(a[1]), "r"(a[2]), "r"(a[3]), "r"(b[0]), "r"(b[1]));
}
__device__ __forceinline__ void mma16(float* d, const unsigned* a, const unsigned* b) {
    asm volatile(
        "mma.sync.aligned.m16n8k16.row.col.f32.bf16.bf16.f32 "
        "{%0,%1,%2,%3}, {%4,%5,%6,%7}, {%8,%9}, {%0,%1,%2,%3};\n"
        : "+f"(d[0]), "+f"(d[1]), "+f"(d[2]), "+f"(d[3])
        : "r"(a[0]), "r"(a[1]), "r"(a[2]), "r"(a[3]), "r"(b[0]), "r"(b[1]));
}
__device__ __forceinline__ unsigned packbf(float lo, float hi) {
    unsigned r;
    asm("cvt.rn.bf16x2.f32 %0, %1, %2;" : "=r"(r) : "f"(hi), "f"(lo));
    return r;
}
__device__ __forceinline__ void ldsm4t(unsigned* r, unsigned addr) {
    asm volatile("ldmatrix.sync.aligned.m8n8.x4.trans.shared.b16 {%0,%1,%2,%3}, [%4];"
                 : "=r"(r[0]), "=r"(r[1]), "=r"(r[2]), "=r"(r[3]) : "r"(addr));
}
__device__ __forceinline__ void cpa16(unsigned saddr, const void* gsrc) {
    asm volatile("cp.async.cg.shared.global [%0], [%1], 16;" :: "r"(saddr), "l"(gsrc));
}
__device__ __forceinline__ void cpcommit() { asm volatile("cp.async.commit_group;"); }
template <int N>
__device__ __forceinline__ void cpwait() { asm volatile("cp.async.wait_group %0;" :: "n"(N)); }
__device__ __forceinline__ unsigned fas(float x) { return __float_as_uint(x); }
__device__ __forceinline__ unsigned ldu32(const __nv_bfloat16* p) { return *(const unsigned*)p; }

// ---------------------------------------------------------------------------
__global__ void prep_kernel(const float* __restrict__ Wk, const float* __restrict__ bk,
                            const float* __restrict__ Wq, const float* __restrict__ bq,
                            const float* __restrict__ Wv, const float* __restrict__ bv) {
    int i = blockIdx.x * blockDim.x + threadIdx.x;   // [0, 16384)
    if (i < 64 * 128) { g_W[i] = Wq[i]; g_W[64 * 128 + i] = Wk[i]; }
    g_W[128 * 128 + i] = Wv[i];
    if (i < 64) { g_bias[i] = bq[i]; g_bias[64 + i] = bk[i]; }
    if (i < 128) g_bias[128 + i] = bv[i];
    if (i < NB * NT) g_colsum[i] = 0.0f;
}

// ---------------------------------------------------------------------------
// QKV projection via tf32 mma. out[m][n] = sum_d x[m][d]*W[n][d] + bias[n]
// n<128 -> bf16 to g_QKb;  n>=128 -> fp32 to g_Vf.
__global__ __launch_bounds__(256) void qkv_kernel(const float* __restrict__ mb) {
    __shared__ float Xs[64 * 68];
    __shared__ float Ws[64 * 68];
    int n0 = blockIdx.x * 64, m0 = blockIdx.y * 64;
    int b = m0 >> 12, t0 = m0 & (NT - 1);
    const float* x = mb + (size_t)b * ND * NT;
    int tid = threadIdx.x, lane = tid & 31, w = tid >> 5;
    int g = lane >> 2, tg = lane & 3;
    int wr = w & 3, wc = w >> 2;
    float acc[4][4] = {};

    for (int k0 = 0; k0 < 128; k0 += 64) {
        __syncthreads();
#pragma unroll
        for (int i = 0; i < 16; i++) {
            int idx = tid + 256 * i;            // 0..4095
            int r = idx & 63, d = idx >> 6;     // d 0..63
            Xs[r * 68 + d] = x[(k0 + d) * NT + t0 + r];
        }
#pragma unroll
        for (int i = 0; i < 16; i++) {
            int idx = tid + 256 * i;
            int dd = idx & 63, n = idx >> 6;
            Ws[n * 68 + dd] = g_W[(n0 + n) * 128 + k0 + dd];
        }
        __syncthreads();
#pragma unroll
        for (int kk = 0; kk < 8; kk++) {
            unsigned a[4];
            a[0] = fas(Xs[(wr * 16 + g) * 68 + kk * 8 + tg]);
            a[1] = fas(Xs[(wr * 16 + g + 8) * 68 + kk * 8 + tg]);
            a[2] = fas(Xs[(wr * 16 + g) * 68 + kk * 8 + tg + 4]);
            a[3] = fas(Xs[(wr * 16 + g + 8) * 68 + kk * 8 + tg + 4]);
#pragma unroll
            for (int ni = 0; ni < 4; ni++) {
                unsigned b2[2];
                b2[0] = fas(Ws[(wc * 32 + ni * 8 + g) * 68 + kk * 8 + tg]);
                b2[1] = fas(Ws[(wc * 32 + ni * 8 + g) * 68 + kk * 8 + tg + 4]);
                mma8(acc[ni], a, b2);
            }
        }
    }
    // epilogue
#pragma unroll
    for (int ni = 0; ni < 4; ni++) {
        int n = n0 + wc * 32 + ni * 8 + 2 * tg;   // even
        float b0 = g_bias[n], b1 = g_bias[n + 1];
        int r1 = m0 + wr * 16 + g, r2 = r1 + 8;
        if (n0 < 128) {
            *(unsigned*)&g_QKb[(size_t)r1 * 128 + n] = packbf(acc[ni][0] + b0, acc[ni][1] + b1);
            *(unsigned*)&g_QKb[(size_t)r2 * 128 + n] = packbf(acc[ni][2] + b0, acc[ni][3] + b1);
        } else {
            *(float2*)&g_Vf[(size_t)r1 * 128 + n - 128] =
                make_float2(acc[ni][0] + b0, acc[ni][1] + b1);
            *(float2*)&g_Vf[(size_t)r2 * 128 + n - 128] =
                make_float2(acc[ni][2] + b0, acc[ni][3] + b1);
        }
    }
}

// ---------------------------------------------------------------------------
// colsum[b][t] = sum_{q>=t} exp(Q[q].K[t]) — bf16 mma16 + cp.async pipelined Q.
__global__ __launch_bounds__(256) void colsum_kernel() {
    const int QCHUNK = 512;
    int t0 = blockIdx.x * 64, b = blockIdx.y, qlo = blockIdx.z * QCHUNK;
    if (qlo + QCHUNK - 1 < t0) return;
    __shared__ __align__(16) __nv_bfloat16 Ksm[64 * 72];
    __shared__ __align__(16) __nv_bfloat16 Qsm[2][64 * 72];
    __shared__ float cs[64];
    const __nv_bfloat16* qk = g_QKb + (size_t)b * NT * 128;
    int tid = threadIdx.x, lane = tid & 31, w = tid >> 5;
    int g = lane >> 2, tg = lane & 3, wr = w & 1, wc = w >> 1;
    unsigned sbq = (unsigned)__cvta_generic_to_shared(&Qsm[0][0]);

    { int c = tid & 7, r0 = tid >> 3;            // K tile (once)
#pragma unroll
      for (int i = 0; i < 2; i++) { int r = r0 + 32 * i;
          *(uint4*)&Ksm[r * 72 + c * 8] = *(const uint4*)&qk[(size_t)(t0 + r) * 128 + 64 + c * 8]; } }
    if (tid < 64) cs[tid] = 0.0f;
    { int c = tid & 7, r0 = tid >> 3;            // prefetch Q tile 0
#pragma unroll
      for (int i = 0; i < 2; i++) { int r = r0 + 32 * i;
          cpa16(sbq + (r * 72 + c * 8) * 2, qk + (size_t)(qlo + r) * 128 + c * 8); } }
    cpcommit();
    __syncthreads();

    unsigned bf[2][4][2];                        // hoisted K B-frags
#pragma unroll
    for (int ni = 0; ni < 2; ni++)
#pragma unroll
        for (int kk2 = 0; kk2 < 4; kk2++) {
            int n = wc * 16 + ni * 8 + g;
            bf[ni][kk2][0] = ldu32(&Ksm[n * 72 + kk2 * 16 + 2 * tg]);
            bf[ni][kk2][1] = ldu32(&Ksm[n * 72 + kk2 * 16 + 8 + 2 * tg]);
        }

    float colacc[2][2] = {};
    int buf = 0;
    for (int q0 = qlo; q0 < qlo + QCHUNK; q0 += 64) {
        if (q0 + 64 < qlo + QCHUNK) {
            int c = tid & 7, r0 = tid >> 3, bo = buf ^ 1;
#pragma unroll
            for (int i = 0; i < 2; i++) { int r = r0 + 32 * i;
                cpa16(sbq + bo * 9216 + (r * 72 + c * 8) * 2,
                      qk + (size_t)(q0 + 64 + r) * 128 + c * 8); }
        }
        cpcommit(); cpwait<1>(); __syncthreads();
        if (q0 + 63 >= t0) {
            const __nv_bfloat16* Qs = Qsm[buf];
            float d[2][2][4] = {};
#pragma unroll
            for (int kk2 = 0; kk2 < 4; kk2++) {
                unsigned a[2][4];
#pragma unroll
                for (int mi = 0; mi < 2; mi++) {
                    int r = wr * 32 + mi * 16;
                    a[mi][0] = ldu32(&Qs[(r + g) * 72 + kk2 * 16 + 2 * tg]);
                    a[mi][1] = ldu32(&Qs[(r + g + 8) * 72 + kk2 * 16 + 2 * tg]);
                    a[mi][2] = ldu32(&Qs[(r + g) * 72 + kk2 * 16 + 8 + 2 * tg]);
                    a[mi][3] = ldu32(&Qs[(r + g + 8) * 72 + kk2 * 16 + 8 + 2 * tg]);
                }
#pragma unroll
                for (int mi = 0; mi < 2; mi++)
#pragma unroll
                    for (int ni = 0; ni < 2; ni++)
                        mma16(d[mi][ni], a[mi], bf[ni][kk2]);
            }
#pragma unroll
            for (int mi = 0; mi < 2; mi++)
#pragma unroll
                for (int ni = 0; ni < 2; ni++)
#pragma unroll
                    for (int e = 0; e < 4; e++) {
                        int row = q0 + wr * 32 + mi * 16 + g + (e >> 1) * 8;
                        int col = t0 + wc * 16 + ni * 8 + 2 * tg + (e & 1);
                        if (row >= col) colacc[ni][e & 1] += __expf(d[mi][ni][e]);
                    }
        }
        __syncthreads();
        buf ^= 1;
    }
#pragma unroll
    for (int ni = 0; ni < 2; ni++)
#pragma unroll
        for (int j = 0; j < 2; j++) {
            float v = colacc[ni][j];
            v += __shfl_xor_sync(0xffffffffu, v, 4);
            v += __shfl_xor_sync(0xffffffffu, v, 8);
            v += __shfl_xor_sync(0xffffffffu, v, 16);
            colacc[ni][j] = v;
        }
    if (g == 0)
#pragma unroll
        for (int ni = 0; ni < 2; ni++) {
            atomicAdd(&cs[wc * 16 + ni * 8 + 2 * tg], colacc[ni][0]);
            atomicAdd(&cs[wc * 16 + ni * 8 + 2 * tg + 1], colacc[ni][1]);
        }
    __syncthreads();
    if (tid < 64) atomicAdd(&g_colsum[b * NT + t0 + tid], cs[tid]);
}

// ---------------------------------------------------------------------------
// scalev: g_Vsb[b][t][v] = bf16( V / (8*colsum) )
__global__ void scalev_kernel() {
    int idx = blockIdx.x * 256 + threadIdx.x;   // [0, 4*4096*64)
    int v2 = idx & 63;
    int t = (idx >> 6) & (NT - 1);
    int b = idx >> 18;
    float inv = 1.0f / (8.0f * g_colsum[b * NT + t]);
    const float* src = &g_Vf[(((size_t)b * NT + t) << 7) + v2 * 2];
    __nv_bfloat162 o;
    o.x = __float2bfloat16(src[0] * inv);
    o.y = __float2bfloat16(src[1] * inv);
    ((__nv_bfloat162*)g_Vsb)[((size_t)b * NT + t) * 64 + v2] = o;
}

// ---------------------------------------------------------------------------
// attn: block xx handles q-tiles (xx, 63-xx). Warps 0-3 -> tile A, 4-7 -> tile B.
// All-bf16 mma16: S = QK^T (bf16) -> exp in regs -> bf16 A-frags -> EV mma.
// smem bytes: [0,18432) Q tiles (b16 stride 72); [18432,36864) K dbuf;
//             [36864,71680) V dbuf (b16 stride 136). Epilogue reuses [0,69632) f32 staging.
#define AT_KB 18432
#define AT_VB 36864
#define ATT_SMEM 71680

__global__ __launch_bounds__(256, 1) void attn_kernel(const float* __restrict__ mb,
                                                      float* __restrict__ out) {
    extern __shared__ float sm[];
    __nv_bfloat16* smb = (__nv_bfloat16*)sm;
    int xx = blockIdx.x, b = blockIdx.y;
    int qtA = xx, qtB = 63 - xx;
    int q0A = qtA * 64, q0B = qtB * 64;
    const __nv_bfloat16* qk = g_QKb + (size_t)b * NT * 128;
    const __nv_bfloat16* vsb = g_Vsb + (size_t)b * NT * NV;
    int tid = threadIdx.x, lane = tid & 31, w = tid >> 5;
    int g = lane >> 2, tg = lane & 3;
    int gid = w >> 2, wg = w & 3;
    int myqt = gid ? qtB : qtA;
    unsigned sb = (unsigned)__cvta_generic_to_shared(sm);

    // load both Q tiles (bf16, 1024 16B-chunks)
#pragma unroll
    for (int i = 0; i < 4; i++) {
        int idx = tid + 256 * i;
        int grp = idx >> 9, rem = idx & 511, r = rem >> 3, c = rem & 7;
        int q0g = grp ? q0B : q0A;
        *(uint4*)&smb[grp * 4608 + r * 72 + c * 8] =
            *(const uint4*)&qk[(size_t)(q0g + r) * 128 + c * 8];
    }
    // prefetch tile 0 (K + V bf16)
#pragma unroll
    for (int i = 0; i < 2; i++) { int idx = tid + 256 * i; int r = idx >> 3, c = idx & 7;
        cpa16(sb + AT_KB + (r * 72 + c * 8) * 2, qk + (size_t)r * 128 + 64 + c * 8); }
#pragma unroll
    for (int i = 0; i < 4; i++) { int idx = tid + 256 * i; int r = idx >> 4, c = idx & 15;
        cpa16(sb + AT_VB + (r * 136 + c * 8) * 2, vsb + (size_t)r * 128 + c * 8); }
    cpcommit();
    __syncthreads();

    // hoist Q A-fragments (bf16)
    const __nv_bfloat16* myQ = smb + gid * 4608;
    unsigned qa_[4][4];
#pragma unroll
    for (int kk2 = 0; kk2 < 4; kk2++) {
        int r = wg * 16;
        qa_[kk2][0] = ldu32(&myQ[(r + g) * 72 + kk2 * 16 + 2 * tg]);
        qa_[kk2][1] = ldu32(&myQ[(r + g + 8) * 72 + kk2 * 16 + 2 * tg]);
        qa_[kk2][2] = ldu32(&myQ[(r + g) * 72 + kk2 * 16 + 8 + 2 * tg]);
        qa_[kk2][3] = ldu32(&myQ[(r + g + 8) * 72 + kk2 * 16 + 8 + 2 * tg]);
    }

    float acc[16][4] = {};
    int buf = 0;
    int sub = lane >> 3, li = lane & 7;
    for (int tt = 0; tt <= qtB; tt++) {
        if (tt < qtB) {
            int t1 = (tt + 1) * 64, bo = buf ^ 1;
#pragma unroll
            for (int i = 0; i < 2; i++) { int idx = tid + 256 * i; int r = idx >> 3, c = idx & 7;
                cpa16(sb + AT_KB + bo * 9216 + (r * 72 + c * 8) * 2,
                      qk + (size_t)(t1 + r) * 128 + 64 + c * 8); }
#pragma unroll
            for (int i = 0; i < 4; i++) { int idx = tid + 256 * i; int r = idx >> 4, c = idx & 15;
                cpa16(sb + AT_VB + bo * 17408 + (r * 136 + c * 8) * 2,
                      vsb + (size_t)(t1 + r) * 128 + c * 8); }
        }
        cpcommit(); cpwait<1>(); __syncthreads();

        if (tt <= myqt) {
            const __nv_bfloat16* Kb = smb + (AT_KB / 2) + buf * 4608;
            float d[8][4] = {};
#pragma unroll
            for (int kk2 = 0; kk2 < 4; kk2++)
#pragma unroll
                for (int ni = 0; ni < 8; ni++) {
                    unsigned b2[2] = { ldu32(&Kb[(ni * 8 + g) * 72 + kk2 * 16 + 2 * tg]),
                                       ldu32(&Kb[(ni * 8 + g) * 72 + kk2 * 16 + 8 + 2 * tg]) };
                    mma16(d[ni], qa_[kk2], b2);
                }
            bool diag = (tt == myqt);
            unsigned Af[4][4];
#pragma unroll
            for (int ni = 0; ni < 8; ni++) {
                float e[4];
#pragma unroll
                for (int c = 0; c < 4; c++) {
                    int row = wg * 16 + g + (c >> 1) * 8;
                    int col = ni * 8 + 2 * tg + (c & 1);
                    float v = __expf(d[ni][c]);
                    e[c] = (diag && col > row) ? 0.0f : v;
                }
                Af[ni >> 1][(ni & 1) * 2 + 0] = packbf(e[0], e[1]);
                Af[ni >> 1][(ni & 1) * 2 + 1] = packbf(e[2], e[3]);
            }
#pragma unroll
            for (int kc = 0; kc < 4; kc++)
#pragma unroll
                for (int nj = 0; nj < 8; nj++) {
                    unsigned r4[4];
                    unsigned addr = sb + AT_VB + buf * 17408 +
                        ((kc * 16 + (sub & 1) * 8 + li) * 136 + nj * 16 + (sub >> 1) * 8) * 2;
                    ldsm4t(r4, addr);
                    mma16(acc[nj * 2 + 0], Af[kc], &r4[0]);
                    mma16(acc[nj * 2 + 1], Af[kc], &r4[2]);
                }
        }
        __syncthreads();
        buf ^= 1;
    }

    // epilogue: stage (f32 stride 133), add residual, transposed coalesced write
    float* stg = gid ? (sm + 8704) : sm;
#pragma unroll
    for (int nj = 0; nj < 16; nj++)
#pragma unroll
        for (int c = 0; c < 4; c++) {
            int row = wg * 16 + g + (c >> 1) * 8;
            int col = nj * 8 + 2 * tg + (c & 1);
            stg[row * 133 + col] = acc[nj][c];
        }
    __syncthreads();
    {
        int gw = tid >> 7, gtid = tid & 127;
        int qq = gtid & 63, db = gtid >> 6;
        const float* s2 = gw ? (sm + 8704) : sm;
        int q0w = gw ? q0B : q0A;
        const float* xin = mb + (size_t)b * ND * NT;
        float* o = out + (size_t)b * ND * NT;
#pragma unroll
        for (int i = 0; i < 64; i++) {
            int d_ = db + i * 2;
            o[d_ * NT + q0w + qq] = xin[d_ * NT + q0w + qq] + s2[qq * 133 + d_];
        }
    }
}

// ---------------------------------------------------------------------------
extern "C" void kernel_launch(void* const* d_in, const int* in_sizes, int n_in,
                              void* d_out, int out_size) {
    const float* mb = (const float*)d_in[0];
    const float* Wk = (const float*)d_in[1];
    const float* bk = (const float*)d_in[2];
    const float* Wq = (const float*)d_in[3];
    const float* bq = (const float*)d_in[4];
    const float* Wv = (const float*)d_in[5];
    const float* bv = (const float*)d_in[6];
    float* out = (float*)d_out;

    cudaFuncSetAttribute(attn_kernel, cudaFuncAttributeMaxDynamicSharedMemorySize, ATT_SMEM);

    prep_kernel<<<64, 256>>>(Wk, bk, Wq, bq, Wv, bv);
    qkv_kernel<<<dim3(4, 256), 256>>>(mb);
    colsum_kernel<<<dim3(64, 4, 8), 256>>>();
    scalev_kernel<<<(NB * NT * 64) / 256, 256>>>();
    attn_kernel<<<dim3(32, 4), 256, ATT_SMEM>>>(mb, out);
}

// round 7
// speedup vs baseline: 2.0589x; 1.0141x over previous
#include <cuda_runtime.h>
#include <cuda_bf16.h>
#include <math.h>

#define NB 4
#define ND 128
#define NT 4096
#define NK 64
#define NV 128

__device__ float g_W[256 * 128];
__device__ float g_bias[256];
__device__ __nv_bfloat16 g_QKb[NB * NT * 128];  // per row: [Q(64)|K(64)] bf16
__device__ __nv_bfloat16 g_Vb[NB * NT * 128];   // V bf16 (raw)
__device__ float g_colsum[NB * NT];
__device__ float g_inv[NB * NT];                // 1/(8*colsum)

// ---------------------------------------------------------------------------
__device__ __forceinline__ void mma8(float* d, const unsigned* a, const unsigned* b) {
    asm volatile(
        "mma.sync.aligned.m16n8k8.row.col.f32.tf32.tf32.f32 "
        "{%0,%1,%2,%3}, {%4,%5,%6,%7}, {%8,%9}, {%0,%1,%2,%3};\n"
        : "+f"(d[0]), "+f"(d[1]), "+f"(d[2]), "+f"(d[3])
        : "r"(a[0]), "r"(a[1]), "r"(a[2]), "r"(a[3]), "r"(b[0]), "r"(b[1]));
}
__device__ __forceinline__ void mma16(float* d, const unsigned* a, const unsigned* b) {
    asm volatile(
        "mma.sync.aligned.m16n8k16.row.col.f32.bf16.bf16.f32 "
        "{%0,%1,%2,%3}, {%4,%5,%6,%7}, {%8,%9}, {%0,%1,%2,%3};\n"
        : "+f"(d[0]), "+f"(d[1]), "+f"(d[2]), "+f"(d[3])
        : "r"(a[0]), "r"(a[1]), "r"(a[2]), "r"(a[3]), "r"(b[0]), "r"(b[1]));
}
__device__ __forceinline__ unsigned packbf(float lo, float hi) {
    unsigned r;
    asm("cvt.rn.bf16x2.f32 %0, %1, %2;" : "=r"(r) : "f"(hi), "f"(lo));
    return r;
}
__device__ __forceinline__ void ldsm4(unsigned* r, unsigned addr) {
    asm volatile("ldmatrix.sync.aligned.m8n8.x4.shared.b16 {%0,%1,%2,%3}, [%4];"
                 : "=r"(r[0]), "=r"(r[1]), "=r"(r[2]), "=r"(r[3]) : "r"(addr));
}
__device__ __forceinline__ void ldsm4t(unsigned* r, unsigned addr) {
    asm volatile("ldmatrix.sync.aligned.m8n8.x4.trans.shared.b16 {%0,%1,%2,%3}, [%4];"
                 : "=r"(r[0]), "=r"(r[1]), "=r"(r[2]), "=r"(r[3]) : "r"(addr));
}
__device__ __forceinline__ void cpa16(unsigned saddr, const void* gsrc) {
    asm volatile("cp.async.cg.shared.global [%0], [%1], 16;" :: "r"(saddr), "l"(gsrc));
}
__device__ __forceinline__ void cpcommit() { asm volatile("cp.async.commit_group;"); }
template <int N>
__device__ __forceinline__ void cpwait() { asm volatile("cp.async.wait_group %0;" :: "n"(N)); }
__device__ __forceinline__ unsigned fas(float x) { return __float_as_uint(x); }
__device__ __forceinline__ unsigned ldu32(const __nv_bfloat16* p) { return *(const unsigned*)p; }

// ---------------------------------------------------------------------------
__global__ void prep_kernel(const float* __restrict__ Wk, const float* __restrict__ bk,
                            const float* __restrict__ Wq, const float* __restrict__ bq,
                            const float* __restrict__ Wv, const float* __restrict__ bv) {
    int i = blockIdx.x * blockDim.x + threadIdx.x;   // [0, 16384)
    if (i < 64 * 128) { g_W[i] = Wq[i]; g_W[64 * 128 + i] = Wk[i]; }
    g_W[128 * 128 + i] = Wv[i];
    if (i < 64) { g_bias[i] = bq[i]; g_bias[64 + i] = bk[i]; }
    if (i < 128) g_bias[128 + i] = bv[i];
    if (i < NB * NT) g_colsum[i] = 0.0f;
}

// ---------------------------------------------------------------------------
// QKV via tf32 mma. n<128 -> bf16 Q|K;  n>=128 -> bf16 V (raw).
__global__ __launch_bounds__(256) void qkv_kernel(const float* __restrict__ mb) {
    __shared__ float Xs[64 * 68];
    __shared__ float Ws[64 * 68];
    int n0 = blockIdx.x * 64, m0 = blockIdx.y * 64;
    int b = m0 >> 12, t0 = m0 & (NT - 1);
    const float* x = mb + (size_t)b * ND * NT;
    int tid = threadIdx.x, lane = tid & 31, w = tid >> 5;
    int g = lane >> 2, tg = lane & 3;
    int wr = w & 3, wc = w >> 2;
    float acc[4][4] = {};

    for (int k0 = 0; k0 < 128; k0 += 64) {
        __syncthreads();
#pragma unroll
        for (int i = 0; i < 16; i++) {
            int idx = tid + 256 * i;
            int r = idx & 63, d = idx >> 6;
            Xs[r * 68 + d] = x[(k0 + d) * NT + t0 + r];
        }
#pragma unroll
        for (int i = 0; i < 16; i++) {
            int idx = tid + 256 * i;
            int dd = idx & 63, n = idx >> 6;
            Ws[n * 68 + dd] = g_W[(n0 + n) * 128 + k0 + dd];
        }
        __syncthreads();
#pragma unroll
        for (int kk = 0; kk < 8; kk++) {
            unsigned a[4];
            a[0] = fas(Xs[(wr * 16 + g) * 68 + kk * 8 + tg]);
            a[1] = fas(Xs[(wr * 16 + g + 8) * 68 + kk * 8 + tg]);
            a[2] = fas(Xs[(wr * 16 + g) * 68 + kk * 8 + tg + 4]);
            a[3] = fas(Xs[(wr * 16 + g + 8) * 68 + kk * 8 + tg + 4]);
#pragma unroll
            for (int ni = 0; ni < 4; ni++) {
                unsigned b2[2];
                b2[0] = fas(Ws[(wc * 32 + ni * 8 + g) * 68 + kk * 8 + tg]);
                b2[1] = fas(Ws[(wc * 32 + ni * 8 + g) * 68 + kk * 8 + tg + 4]);
                mma8(acc[ni], a, b2);
            }
        }
    }
#pragma unroll
    for (int ni = 0; ni < 4; ni++) {
        int n = n0 + wc * 32 + ni * 8 + 2 * tg;   // even
        float b0 = g_bias[n], b1 = g_bias[n + 1];
        int r1 = m0 + wr * 16 + g, r2 = r1 + 8;
        if (n0 < 128) {
            *(unsigned*)&g_QKb[(size_t)r1 * 128 + n] = packbf(acc[ni][0] + b0, acc[ni][1] + b1);
            *(unsigned*)&g_QKb[(size_t)r2 * 128 + n] = packbf(acc[ni][2] + b0, acc[ni][3] + b1);
        } else {
            *(unsigned*)&g_Vb[(size_t)r1 * 128 + n - 128] = packbf(acc[ni][0] + b0, acc[ni][1] + b1);
            *(unsigned*)&g_Vb[(size_t)r2 * 128 + n - 128] = packbf(acc[ni][2] + b0, acc[ni][3] + b1);
        }
    }
}

// ---------------------------------------------------------------------------
// colsum[b][t] = sum_{q>=t} exp(Q[q].K[t]) — bf16 mma16, ldmatrix A-frags.
__global__ __launch_bounds__(256) void colsum_kernel() {
    const int QCHUNK = 512;
    int t0 = blockIdx.x * 64, b = blockIdx.y, qlo = blockIdx.z * QCHUNK;
    if (qlo + QCHUNK - 1 < t0) return;
    __shared__ __align__(16) __nv_bfloat16 Ksm[64 * 72];
    __shared__ __align__(16) __nv_bfloat16 Qsm[2][64 * 72];
    __shared__ float cs[64];
    const __nv_bfloat16* qk = g_QKb + (size_t)b * NT * 128;
    int tid = threadIdx.x, lane = tid & 31, w = tid >> 5;
    int g = lane >> 2, tg = lane & 3, wr = w & 1, wc = w >> 1;
    unsigned sbq = (unsigned)__cvta_generic_to_shared(&Qsm[0][0]);
    unsigned sbQ0 = sbq;

    { int c = tid & 7, r0 = tid >> 3;            // K tile (once)
#pragma unroll
      for (int i = 0; i < 2; i++) { int r = r0 + 32 * i;
          *(uint4*)&Ksm[r * 72 + c * 8] = *(const uint4*)&qk[(size_t)(t0 + r) * 128 + 64 + c * 8]; } }
    if (tid < 64) cs[tid] = 0.0f;
    { int c = tid & 7, r0 = tid >> 3;            // prefetch Q tile 0
#pragma unroll
      for (int i = 0; i < 2; i++) { int r = r0 + 32 * i;
          cpa16(sbq + (r * 72 + c * 8) * 2, qk + (size_t)(qlo + r) * 128 + c * 8); } }
    cpcommit();
    __syncthreads();

    unsigned bf[2][4][2];                        // hoisted K B-frags
#pragma unroll
    for (int ni = 0; ni < 2; ni++)
#pragma unroll
        for (int kk2 = 0; kk2 < 4; kk2++) {
            int n = wc * 16 + ni * 8 + g;
            bf[ni][kk2][0] = ldu32(&Ksm[n * 72 + kk2 * 16 + 2 * tg]);
            bf[ni][kk2][1] = ldu32(&Ksm[n * 72 + kk2 * 16 + 8 + 2 * tg]);
        }

    float colacc[2][2] = {};
    int buf = 0;
    // ldmatrix A address pieces: row = base + (l&7) + ((l>>3)&1)*8 ; col = kk2*16 + (l>>4)*8
    int arow = (lane & 7) + ((lane >> 3) & 1) * 8;
    int acol = (lane >> 4) * 8;
    for (int q0 = qlo; q0 < qlo + QCHUNK; q0 += 64) {
        if (q0 + 64 < qlo + QCHUNK) {
            int c = tid & 7, r0 = tid >> 3, bo = buf ^ 1;
#pragma unroll
            for (int i = 0; i < 2; i++) { int r = r0 + 32 * i;
                cpa16(sbq + bo * 9216 + (r * 72 + c * 8) * 2,
                      qk + (size_t)(q0 + 64 + r) * 128 + c * 8); }
        }
        cpcommit(); cpwait<1>(); __syncthreads();
        if (q0 + 63 >= t0) {
            unsigned qbase = sbQ0 + buf * 9216;
            float d[2][2][4] = {};
#pragma unroll
            for (int kk2 = 0; kk2 < 4; kk2++) {
                unsigned a[2][4];
#pragma unroll
                for (int mi = 0; mi < 2; mi++) {
                    int r = wr * 32 + mi * 16 + arow;
                    ldsm4(a[mi], qbase + (r * 72 + kk2 * 16 + acol) * 2);
                }
#pragma unroll
                for (int mi = 0; mi < 2; mi++)
#pragma unroll
                    for (int ni = 0; ni < 2; ni++)
                        mma16(d[mi][ni], a[mi], bf[ni][kk2]);
            }
#pragma unroll
            for (int mi = 0; mi < 2; mi++)
#pragma unroll
                for (int ni = 0; ni < 2; ni++)
#pragma unroll
                    for (int e = 0; e < 4; e++) {
                        int row = q0 + wr * 32 + mi * 16 + g + (e >> 1) * 8;
                        int col = t0 + wc * 16 + ni * 8 + 2 * tg + (e & 1);
                        if (row >= col) colacc[ni][e & 1] += __expf(d[mi][ni][e]);
                    }
        }
        __syncthreads();
        buf ^= 1;
    }
#pragma unroll
    for (int ni = 0; ni < 2; ni++)
#pragma unroll
        for (int j = 0; j < 2; j++) {
            float v = colacc[ni][j];
            v += __shfl_xor_sync(0xffffffffu, v, 4);
            v += __shfl_xor_sync(0xffffffffu, v, 8);
            v += __shfl_xor_sync(0xffffffffu, v, 16);
            colacc[ni][j] = v;
        }
    if (g == 0)
#pragma unroll
        for (int ni = 0; ni < 2; ni++) {
            atomicAdd(&cs[wc * 16 + ni * 8 + 2 * tg], colacc[ni][0]);
            atomicAdd(&cs[wc * 16 + ni * 8 + 2 * tg + 1], colacc[ni][1]);
        }
    __syncthreads();
    if (tid < 64) atomicAdd(&g_colsum[b * NT + t0 + tid], cs[tid]);
}

// ---------------------------------------------------------------------------
// inv: g_inv = 1/(8*colsum)
__global__ void inv_kernel() {
    int i = blockIdx.x * 256 + threadIdx.x;
    g_inv[i] = 1.0f / (8.0f * g_colsum[i]);
}

// ---------------------------------------------------------------------------
// attn: block xx handles q-tiles (xx, 63-xx). E scaled by inv8cs[t] in regs.
// smem bytes: [0,18432) Q; [18432,36864) K dbuf; [36864,71680) V dbuf; [71680,72192) inv dbuf.
#define AT_KB 18432
#define AT_VB 36864
#define AT_IB 71680
#define ATT_SMEM 72192

__global__ __launch_bounds__(256, 1) void attn_kernel(const float* __restrict__ mb,
                                                      float* __restrict__ out) {
    extern __shared__ float sm[];
    __nv_bfloat16* smb = (__nv_bfloat16*)sm;
    float* invs = (float*)((char*)sm + AT_IB);
    int xx = blockIdx.x, b = blockIdx.y;
    int qtA = xx, qtB = 63 - xx;
    int q0A = qtA * 64, q0B = qtB * 64;
    const __nv_bfloat16* qk = g_QKb + (size_t)b * NT * 128;
    const __nv_bfloat16* vsb = g_Vb + (size_t)b * NT * 128;
    const float* invp = g_inv + (size_t)b * NT;
    int tid = threadIdx.x, lane = tid & 31, w = tid >> 5;
    int g = lane >> 2, tg = lane & 3;
    int gid = w >> 2, wg = w & 3;
    int myqt = gid ? qtB : qtA;
    unsigned sb = (unsigned)__cvta_generic_to_shared(sm);

    // load both Q tiles (bf16)
#pragma unroll
    for (int i = 0; i < 4; i++) {
        int idx = tid + 256 * i;
        int grp = idx >> 9, rem = idx & 511, r = rem >> 3, c = rem & 7;
        int q0g = grp ? q0B : q0A;
        *(uint4*)&smb[grp * 4608 + r * 72 + c * 8] =
            *(const uint4*)&qk[(size_t)(q0g + r) * 128 + c * 8];
    }
    // prefetch tile 0 (K + V + inv)
#pragma unroll
    for (int i = 0; i < 2; i++) { int idx = tid + 256 * i; int r = idx >> 3, c = idx & 7;
        cpa16(sb + AT_KB + (r * 72 + c * 8) * 2, qk + (size_t)r * 128 + 64 + c * 8); }
#pragma unroll
    for (int i = 0; i < 4; i++) { int idx = tid + 256 * i; int r = idx >> 4, c = idx & 15;
        cpa16(sb + AT_VB + (r * 136 + c * 8) * 2, vsb + (size_t)r * 128 + c * 8); }
    if (tid < 16) cpa16(sb + AT_IB + tid * 16, invp + tid * 4);
    cpcommit();
    __syncthreads();

    // hoist Q A-fragments (bf16, via ldmatrix)
    int arow = (lane & 7) + ((lane >> 3) & 1) * 8;
    int acol = (lane >> 4) * 8;
    unsigned qbase = sb + gid * 9216;
    unsigned qa_[4][4];
#pragma unroll
    for (int kk2 = 0; kk2 < 4; kk2++)
        ldsm4(qa_[kk2], qbase + ((wg * 16 + arow) * 72 + kk2 * 16 + acol) * 2);

    // K ldmatrix address pieces: n = (l>>4)*8 + (l&7); k = ((l>>3)&1)*8
    int krow = ((lane >> 4) << 3) + (lane & 7);
    int kcol = ((lane >> 3) & 1) * 8;

    float acc[16][4] = {};
    int buf = 0;
    int sub = lane >> 3, li = lane & 7;
    for (int tt = 0; tt <= qtB; tt++) {
        if (tt < qtB) {
            int t1 = (tt + 1) * 64, bo = buf ^ 1;
#pragma unroll
            for (int i = 0; i < 2; i++) { int idx = tid + 256 * i; int r = idx >> 3, c = idx & 7;
                cpa16(sb + AT_KB + bo * 9216 + (r * 72 + c * 8) * 2,
                      qk + (size_t)(t1 + r) * 128 + 64 + c * 8); }
#pragma unroll
            for (int i = 0; i < 4; i++) { int idx = tid + 256 * i; int r = idx >> 4, c = idx & 15;
                cpa16(sb + AT_VB + bo * 17408 + (r * 136 + c * 8) * 2,
                      vsb + (size_t)(t1 + r) * 128 + c * 8); }
            if (tid < 16) cpa16(sb + AT_IB + bo * 256 + tid * 16, invp + t1 + tid * 4);
        }
        cpcommit(); cpwait<1>(); __syncthreads();

        if (tt <= myqt) {
            unsigned kbase = sb + AT_KB + buf * 9216;
            float d[8][4] = {};
#pragma unroll
            for (int kk2 = 0; kk2 < 4; kk2++)
#pragma unroll
                for (int nb = 0; nb < 4; nb++) {
                    unsigned r4[4];
                    ldsm4(r4, kbase + ((nb * 16 + krow) * 72 + kk2 * 16 + kcol) * 2);
                    mma16(d[nb * 2 + 0], qa_[kk2], &r4[0]);
                    mma16(d[nb * 2 + 1], qa_[kk2], &r4[2]);
                }
            bool diag = (tt == myqt);
            const float* ivt = invs + buf * 64;
            unsigned Af[4][4];
#pragma unroll
            for (int ni = 0; ni < 8; ni++) {
                float2 iv = *(const float2*)&ivt[ni * 8 + 2 * tg];
                float e[4];
#pragma unroll
                for (int c = 0; c < 4; c++) {
                    int row = wg * 16 + g + (c >> 1) * 8;
                    int col = ni * 8 + 2 * tg + (c & 1);
                    float v = __expf(d[ni][c]) * ((c & 1) ? iv.y : iv.x);
                    e[c] = (diag && col > row) ? 0.0f : v;
                }
                Af[ni >> 1][(ni & 1) * 2 + 0] = packbf(e[0], e[1]);
                Af[ni >> 1][(ni & 1) * 2 + 1] = packbf(e[2], e[3]);
            }
#pragma unroll
            for (int kc = 0; kc < 4; kc++)
#pragma unroll
                for (int nj = 0; nj < 8; nj++) {
                    unsigned r4[4];
                    unsigned addr = sb + AT_VB + buf * 17408 +
                        ((kc * 16 + (sub & 1) * 8 + li) * 136 + nj * 16 + (sub >> 1) * 8) * 2;
                    ldsm4t(r4, addr);
                    mma16(acc[nj * 2 + 0], Af[kc], &r4[0]);
                    mma16(acc[nj * 2 + 1], Af[kc], &r4[2]);
                }
        }
        __syncthreads();
        buf ^= 1;
    }

    // epilogue: stage (f32 stride 133), add residual, transposed coalesced write
    float* stg = gid ? (sm + 8704) : sm;
#pragma unroll
    for (int nj = 0; nj < 16; nj++)
#pragma unroll
        for (int c = 0; c < 4; c++) {
            int row = wg * 16 + g + (c >> 1) * 8;
            int col = nj * 8 + 2 * tg + (c & 1);
            stg[row * 133 + col] = acc[nj][c];
        }
    __syncthreads();
    {
        int gw = tid >> 7, gtid = tid & 127;
        int qq = gtid & 63, db = gtid >> 6;
        const float* s2 = gw ? (sm + 8704) : sm;
        int q0w = gw ? q0B : q0A;
        const float* xin = mb + (size_t)b * ND * NT;
        float* o = out + (size_t)b * ND * NT;
#pragma unroll
        for (int i = 0; i < 64; i++) {
            int d_ = db + i * 2;
            o[d_ * NT + q0w + qq] = xin[d_ * NT + q0w + qq] + s2[qq * 133 + d_];
        }
    }
}

// ---------------------------------------------------------------------------
extern "C" void kernel_launch(void* const* d_in, const int* in_sizes, int n_in,
                              void* d_out, int out_size) {
    const float* mb = (const float*)d_in[0];
    const float* Wk = (const float*)d_in[1];
    const float* bk = (const float*)d_in[2];
    const float* Wq = (const float*)d_in[3];
    const float* bq = (const float*)d_in[4];
    const float* Wv = (const float*)d_in[5];
    const float* bv = (const float*)d_in[6];
    float* out = (float*)d_out;

    cudaFuncSetAttribute(attn_kernel, cudaFuncAttributeMaxDynamicSharedMemorySize, ATT_SMEM);

    prep_kernel<<<64, 256>>>(Wk, bk, Wq, bq, Wv, bv);
    qkv_kernel<<<dim3(4, 256), 256>>>(mb);
    colsum_kernel<<<dim3(64, 4, 8), 256>>>();
    inv_kernel<<<(NB * NT) / 256, 256>>>();
    attn_kernel<<<dim3(32, 4), 256, ATT_SMEM>>>(mb, out);
}